// round 14
// baseline (speedup 1.0000x reference)
#include <cuda_runtime.h>
#include <cuda_fp16.h>
#include <cstdint>

// Problem constants
#define B_    4096
#define NM_   25
#define C_    64
#define NNZ_  1000
#define NW_   55
#define NNZP_ 1024          // padded (8 warps x 128 entries)
#define EPW_  128           // entries per warp slice
#define NBINP 640

#define THR   256           // 8 warps; each warp: 128-entry slice x TWO batches
#define BPB   2
#define GRID  (B_ / BPB)    // 2048

// Reordered tables (batch-independent), rebuilt by prep every launch.
// layout (words): [0 .. 2*NNZP_): per entry {A = o1 | flag<<15 | o2<<16, B = ol | om<<16}
//   o1 = m1*256, o2 = m2*256, ol = li*256 (2-batch interleaved half rows), om = mo*256 (fp32 out row)
//                 [2*NNZP_ .. 3*NNZP_): cg bits
__device__ unsigned g_tab[3 * NNZP_];

// ---------------- prep: counting-sort by (mo,m1), pre-shift byte offsets, set load-a flags ----------------
__global__ __launch_bounds__(1024, 1)
void prep_kernel(const float* __restrict__ cg,
                 const int* __restrict__ Mo,  const int* __restrict__ M1,
                 const int* __restrict__ M2,  const int* __restrict__ Li)
{
    __shared__ int      hist[NBINP];
    __shared__ unsigned sA[NNZP_], sB[NNZP_];
    __shared__ float    sC[NNZP_];
    __shared__ short    skey[NNZP_];
    __shared__ int      wsum[32];

    const int tid  = threadIdx.x;
    const int lane = tid & 31;
    const int wrp  = tid >> 5;

    if (tid < NBINP) hist[tid] = 0;
    __syncthreads();

    int key = 0;
    if (tid < NNZ_) {
        key = Mo[tid] * 25 + M1[tid];
        atomicAdd(&hist[key], 1);
    }
    __syncthreads();

    // exclusive scan over 640 bins
    if (wrp < 20) {
        int bin = wrp * 32 + lane;
        int v = hist[bin];
        int inc = v;
        #pragma unroll
        for (int d = 1; d < 32; d <<= 1) {
            int t = __shfl_up_sync(0xFFFFFFFFu, inc, d);
            if (lane >= d) inc += t;
        }
        if (lane == 31) wsum[wrp] = inc;
        hist[bin] = inc - v;
    }
    __syncthreads();
    if (wrp == 0) {
        int v = (lane < 20) ? wsum[lane] : 0;
        int inc = v;
        #pragma unroll
        for (int d = 1; d < 32; d <<= 1) {
            int t = __shfl_up_sync(0xFFFFFFFFu, inc, d);
            if (lane >= d) inc += t;
        }
        if (lane < 20) wsum[lane] = inc - v;
    }
    __syncthreads();
    if (wrp < 20) hist[wrp * 32 + lane] += wsum[wrp];
    __syncthreads();

    // scatter (order within a (mo,m1) bin arbitrary: sum reassociation only)
    if (tid < NNZ_) {
        int idx = atomicAdd(&hist[key], 1);
        sA[idx] = ((unsigned)M1[tid] << 8) | ((unsigned)M2[tid] << (8 + 16));
        sB[idx] = ((unsigned)Li[tid] << 8) | ((unsigned)Mo[tid] << (8 + 16));
        sC[idx] = cg[tid];
        skey[idx] = (short)key;
    }
    __syncthreads();

    // pads + load-a flags (slice boundary every EPW_=128 entries) + writeout
    if (tid < NNZP_) {
        unsigned A, Bw; float Cv;
        if (tid < NNZ_) {
            A = sA[tid]; Bw = sB[tid]; Cv = sC[tid];
            int f = (tid == 0) || ((tid & (EPW_ - 1)) == 0) || (skey[tid] != skey[tid - 1]);
            if (f) A |= 0x8000u;                      // flag in A bit 15
        } else {
            A = 0; Bw = sB[NNZ_ - 1] & 0xFFFF0000u; Cv = 0.f;  // cg=0 dummy, same mo as last
        }
        g_tab[2 * tid]         = A;
        g_tab[2 * tid + 1]     = Bw;
        g_tab[2 * NNZP_ + tid] = __float_as_uint(Cv);
    }
}

// ---------------- main kernel ----------------
// SMEM byte layout (operands half2, 2 batches interleaved per row: row*256 + pair*8 + batch*4):
//  [0,6400)        x1 (25 rows x 256 B)
//  [6400,12800)    x2
//  [12800,26880)   w  (55 rows x 256 B)
//  [26880,35072)   pk (8192 B)
//  [35072,39168)   cg (4096 B)
#define X1OFF   0
#define X2OFF   6400
#define WOFF    12800
#define PKOFF   26880
#define CGOFF   35072
#define SM_BYTES 39168
#define OBSZ    (NM_*C_*4)   // 6400 B: per-batch stride in out

__global__ __launch_bounds__(THR, 5)
void wtp_kernel(const float* __restrict__ x1,
                const float* __restrict__ x2,
                const float* __restrict__ wgt,
                float* __restrict__ out)
{
    extern __shared__ char smem[];
    const int tid  = threadIdx.x;
    const int lane = tid & 31;
    const int wrp  = tid >> 5;
    const int bbase = blockIdx.x * BPB;

    float* outbase = out + (size_t)bbase * NM_ * C_;

    // ---- stage: gather 2 batches per pair-index, interleave, STS.64 ----
    {
        const float2* g10 = (const float2*)(x1 + (size_t)bbase * NM_ * C_);
        const float2* g20 = (const float2*)(x2 + (size_t)bbase * NM_ * C_);
        uint2* d1 = (uint2*)(smem + X1OFF);
        uint2* d2 = (uint2*)(smem + X2OFF);
        for (int i = tid; i < NM_ * C_ / 2; i += THR) {
            float2 a0 = g10[i];
            float2 a1 = g10[i + NM_ * C_ / 2];
            __half2 h0 = __floats2half2_rn(a0.x, a0.y);
            __half2 h1 = __floats2half2_rn(a1.x, a1.y);
            d1[i] = make_uint2(*(unsigned*)&h0, *(unsigned*)&h1);
            float2 b0 = g20[i];
            float2 b1 = g20[i + NM_ * C_ / 2];
            h0 = __floats2half2_rn(b0.x, b0.y);
            h1 = __floats2half2_rn(b1.x, b1.y);
            d2[i] = make_uint2(*(unsigned*)&h0, *(unsigned*)&h1);
        }
        const float2* gw0 = (const float2*)(wgt + (size_t)bbase * NW_ * C_);
        uint2* dw = (uint2*)(smem + WOFF);
        for (int i = tid; i < NW_ * C_ / 2; i += THR) {
            float2 w0 = gw0[i];
            float2 w1 = gw0[i + NW_ * C_ / 2];
            __half2 h0 = __floats2half2_rn(w0.x, w0.y);
            __half2 h1 = __floats2half2_rn(w1.x, w1.y);
            dw[i] = make_uint2(*(unsigned*)&h0, *(unsigned*)&h1);
        }
        // tables: 3072 words = 768 uint4
        const uint4* gt = (const uint4*)g_tab;
        uint4* dt = (uint4*)(smem + PKOFF);
        #pragma unroll 2
        for (int i = tid; i < 3 * NNZP_ / 4; i += THR) dt[i] = gt[i];
        // zero this CTA's output slab (atomics accumulate into zeros)
        float4 z = make_float4(0.f, 0.f, 0.f, 0.f);
        float4* oz = (float4*)outbase;
        for (int i = tid; i < BPB * NM_ * C_ / 4; i += THR) oz[i] = z;
    }
    __syncthreads();

    // ---- per-warp: 128-entry slice, 2 batches; lanes = channel pairs, LDS.64 per operand ----
    const char* p1 = smem + X1OFF + lane * 8;
    const char* p2 = smem + X2OFF + lane * 8;
    const char* pw = smem + WOFF  + lane * 8;
    char* ob = (char*)outbase + lane * 8;

    const unsigned* s_pk = (const unsigned*)(smem + PKOFF);
    const float*    s_cg = (const float*)(smem + CGOFF);

    const int e0 = wrp * EPW_;
    const uint4*  tp = (const uint4*)(s_pk + 2 * e0);
    const float4* tc = (const float4*)(s_cg + e0);

    float ax0=0.f, ay0=0.f, ax1=0.f, ay1=0.f;
    uint2 A2 = make_uint2(0u, 0u);                  // x1 cache (first entry always flagged)
    unsigned cur = s_pk[2 * e0 + 1] >> 16;          // mo*256 of first entry

    // flush: always atomic (segments may straddle warp slices; flushes are rare)
    #define FLUSH() do {                                                      \
        float* d0_ = (float*)(ob + cur);                                      \
        float* d1_ = (float*)(ob + cur + OBSZ);                               \
        atomicAdd(d0_, ax0); atomicAdd(d0_ + 1, ay0);                         \
        atomicAdd(d1_, ax1); atomicAdd(d1_ + 1, ay1);                         \
    } while (0)

    #define STEP(Aw, Bw, CGV) do {                                            \
        unsigned o1_ = (Aw) & 0x3FFFu;                                        \
        unsigned o2_ = (Aw) >> 16;                                            \
        unsigned ol_ = (Bw) & 0xFFFFu;                                        \
        unsigned om_ = (Bw) >> 16;                                            \
        if (om_ != cur) {  /* warp-uniform, rarely taken */                   \
            FLUSH();                                                          \
            ax0=0.f; ay0=0.f; ax1=0.f; ay1=0.f; cur = om_;                    \
        }                                                                     \
        if ((Aw) & 0x8000u) A2 = *(const uint2*)(p1 + o1_);                   \
        uint2 B2 = *(const uint2*)(p2 + o2_);                                 \
        uint2 W2 = *(const uint2*)(pw + ol_);                                 \
        __half2 q0 = __hmul2(__hmul2(*(__half2*)&B2.x, *(__half2*)&W2.x), *(__half2*)&A2.x); \
        __half2 q1 = __hmul2(__hmul2(*(__half2*)&B2.y, *(__half2*)&W2.y), *(__half2*)&A2.y); \
        float2 s0 = __half22float2(q0);                                       \
        float2 s1 = __half22float2(q1);                                       \
        ax0 = fmaf(s0.x, (CGV), ax0);  ay0 = fmaf(s0.y, (CGV), ay0);          \
        ax1 = fmaf(s1.x, (CGV), ax1);  ay1 = fmaf(s1.y, (CGV), ay1);          \
    } while (0)

    #pragma unroll 4
    for (int q = 0; q < EPW_ / 4; ++q) {
        uint4  u0 = tp[2*q];
        uint4  u1 = tp[2*q + 1];
        float4 c4 = tc[q];
        STEP(u0.x, u0.y, c4.x);
        STEP(u0.z, u0.w, c4.y);
        STEP(u1.x, u1.y, c4.z);
        STEP(u1.z, u1.w, c4.w);
    }
    FLUSH();   // final segment
}

extern "C" void kernel_launch(void* const* d_in, const int* in_sizes, int n_in,
                              void* d_out, int out_size)
{
    const float* x1  = (const float*)d_in[0];
    const float* x2  = (const float*)d_in[1];
    const float* wgt = (const float*)d_in[2];
    const float* cg  = (const float*)d_in[3];
    const int*   Mo  = (const int*)d_in[4];
    const int*   M1  = (const int*)d_in[5];
    const int*   M2  = (const int*)d_in[6];
    const int*   Li  = (const int*)d_in[7];
    float* out = (float*)d_out;

    prep_kernel<<<1, 1024>>>(cg, Mo, M1, M2, Li);
    cudaFuncSetAttribute(wtp_kernel, cudaFuncAttributeMaxDynamicSharedMemorySize, SM_BYTES);
    wtp_kernel<<<GRID, THR, SM_BYTES>>>(x1, x2, wgt, out);
}